// round 9
// baseline (speedup 1.0000x reference)
#include <cuda_runtime.h>
#include <cstdint>
#include <cstddef>

// SimpleUpscaleConv2d: y = conv3x3(pad=1, upsample2x_nearest(x), w*WSCALE) + bias
// x[8,16,512,512] f32, w[16,16,3,3] f32, bias[16] f32, out[8,16,1024,1024] f32.
//
// Parity factorization (64 MACs/output, fma.rn.f32x2 over oc-pairs).
// R7: register diet. Chunk maps compressed to u32 offsets + one validity
// bitmask; __launch_bounds__(256,3) restores 3 blocks/SM (R5->R7 lost
// occupancy 36->24% to 102 regs, which capped issue at 50%).

#define RB 4          // input rows per tile (=> 2*RB output rows)
#define TW 32         // input cols per tile (=> 64 output cols)
#define NT 4          // tiles per block (row direction)

#define TH  6         // RB + 2 halo rows
#define TCC 40        // padded row: cols [j0-4, j0+36), halo col j0-1 at idx 3
#define TILE_ELEMS (16 * TH * TCC)            // 3840 floats
#define TILE_CHUNKS (16 * TH * (TCC / 4))     // 960 16B chunks

typedef unsigned long long u64;

__device__ __align__(16) float g_weff[4096]; // [ic][py][px][ty][g][tx][u]

__device__ __forceinline__ u64 pack2(float a, float b) {
    u64 r; asm("mov.b64 %0, {%1, %2};" : "=l"(r) : "f"(a), "f"(b)); return r;
}
__device__ __forceinline__ float2 unpack2(u64 v) {
    float2 r; asm("mov.b64 {%0, %1}, %2;" : "=f"(r.x), "=f"(r.y) : "l"(v)); return r;
}
__device__ __forceinline__ void fma2(u64& d, u64 a, u64 b) {
    asm("fma.rn.f32x2 %0, %1, %2, %0;" : "+l"(d) : "l"(a), "l"(b));
}
__device__ __forceinline__ void cp_async16(uint32_t saddr, const void* gaddr, uint32_t sz) {
    asm volatile("cp.async.cg.shared.global [%0], [%1], 16, %2;"
                 :: "r"(saddr), "l"(gaddr), "r"(sz));
}
__device__ __forceinline__ void cp_commit() {
    asm volatile("cp.async.commit_group;" ::: "memory");
}
template <int N>
__device__ __forceinline__ void cp_wait() {
    asm volatile("cp.async.wait_group %0;" :: "n"(N) : "memory");
}

// ---------------------------------------------------------------------------
// Pre-kernel: parity-combined, wscale-folded weights.
// Stride: u:1, tx:2, g:4, ty:32, px:64, py:128, ic:256  (4096 floats)
// ---------------------------------------------------------------------------
__global__ void build_weff_kernel(const float* __restrict__ w) {
    int idx = blockIdx.x * 256 + threadIdx.x;
    if (idx >= 4096) return;
    int u  = idx & 1;
    int tx = (idx >> 1) & 1;
    int g  = (idx >> 2) & 7;
    int ty = (idx >> 5) & 1;
    int px = (idx >> 6) & 1;
    int py = (idx >> 7) & 1;
    int ic = idx >> 8;
    int oc = 2 * g + u;

    int ky_lo = (py == 0) ? (ty == 0 ? 0 : 1) : 0;
    int ky_hi = (py == 0) ? (ty == 0 ? 0 : 2) : (ty == 0 ? 1 : 2);
    if (py == 1 && ty == 1) ky_lo = 2;
    int kx_lo = (px == 0) ? (tx == 0 ? 0 : 1) : 0;
    int kx_hi = (px == 0) ? (tx == 0 ? 0 : 2) : (tx == 0 ? 1 : 2);
    if (px == 1 && tx == 1) kx_lo = 2;

    const float WS = (float)(1.4142135623730951 / 12.0);  // sqrt(2)/sqrt(16*9)
    float s = 0.f;
    for (int ky = ky_lo; ky <= ky_hi; ky++)
        for (int kx = kx_lo; kx <= kx_hi; kx++)
            s += w[((oc * 16 + ic) * 3 + ky) * 3 + kx];
    g_weff[idx] = s * WS;
}

// ---------------------------------------------------------------------------
// Main kernel. 256 threads = 8 warps; warp g owns oc-pair {2g, 2g+1} in the
// f32x2 lanes; lane = column. NT row-tiles per block, double-buffered 16B
// cp.async staging, compressed chunk maps + validity bitmask.
// ---------------------------------------------------------------------------
__global__ void __launch_bounds__(256, 3) upconv_kernel(
    const float* __restrict__ x,
    const float* __restrict__ bias,
    float* __restrict__ out)
{
    __shared__ __align__(16) float s_w[4096];
    __shared__ __align__(16) float s_in[2][TILE_ELEMS];

    const int tid  = threadIdx.x;
    const int lane = tid & 31;
    const int g    = tid >> 5;
    const int j0   = blockIdx.x * TW;
    const int iB   = blockIdx.y * (NT * RB);
    const int n    = blockIdx.z;

    const float* xb = x + (size_t)n * 16 * 512 * 512;
    float* ob       = out + (size_t)n * 16 * 1024 * 1024;

    uint32_t sw_base  = (uint32_t)__cvta_generic_to_shared(s_w);
    uint32_t sin_base = (uint32_t)__cvta_generic_to_shared(s_in);

    // ---- compressed staging chunk map ----
    // chunk c = tid + k*256: ic=c/60, rr=(c%60)/10, ch=c%10
    // smem byte off = ((ic*6+rr)*40 + ch*4)*4 ; global byte off from xb
    // validity bit (k*4+t): live && colok && 0<=iB-1+rr+t*RB<512
    uint32_t c_soff[4];
    int32_t  c_goff[4];          // byte offset from xb (may be negative)
    uint32_t vmask = 0;
    #pragma unroll
    for (int k = 0; k < 4; k++) {
        int c = tid + k * 256;
        bool live = (c < TILE_CHUNKS);
        int cc = live ? c : 0;
        int ic = cc / 60;
        int r6 = cc - ic * 60;
        int rr = r6 / 10;
        int ch = r6 - rr * 10;
        c_soff[k] = (uint32_t)(((ic * TH + rr) * TCC + ch * 4) * 4);
        int colb  = j0 - 4 + ch * 4;
        bool colok = ((unsigned)colb <= 508u);
        int row0  = iB - 1 + rr;
        c_goff[k] = (ic * 262144 + row0 * 512 + colb) * 4;
        #pragma unroll
        for (int t = 0; t < NT; t++) {
            bool rowok = ((unsigned)(row0 + t * RB) < 512u);
            if (live && colok && rowok) vmask |= 1u << (k * 4 + t);
        }
    }
    const int t_stride = RB * 512 * 4;   // bytes per tile step

    // ---- async stage: weights (4x 16B per thread) + tile 0 ----
    #pragma unroll
    for (int k = 0; k < 4; k++) {
        int idx = (tid + k * 256) * 4;
        cp_async16(sw_base + idx * 4, &g_weff[idx], 16);
    }

    auto stage_tile = [&](int t, int b) {
        const char* xc = (const char*)xb;
        #pragma unroll
        for (int k = 0; k < 4; k++) {
            if (k == 3 && tid >= TILE_CHUNKS - 768) break;   // dead chunks
            bool ok = (vmask >> (k * 4 + t)) & 1u;
            const void* gp = ok ? (const void*)(xc + c_goff[k] + t * t_stride)
                                : (const void*)xc;
            cp_async16(sin_base + (uint32_t)(b * (TILE_ELEMS * 4)) + c_soff[k],
                       gp, ok ? 16u : 0u);
        }
    };

    stage_tile(0, 0);
    cp_commit();

    const u64 binit = pack2(bias[2 * g], bias[2 * g + 1]);
    float* obase = ob + (size_t)(2 * g) * 1048576 + 2 * (j0 + lane);

#define LOAD_ROW(dst, rr) do {                                   \
    float a0 = sbuf[(rr) * TCC + (lane + 3) + icoff];            \
    float a1 = sbuf[(rr) * TCC + (lane + 4) + icoff];            \
    float a2 = sbuf[(rr) * TCC + (lane + 5) + icoff];            \
    dst[0] = pack2(a0, a0);                                      \
    dst[1] = pack2(a1, a1);                                      \
    dst[2] = pack2(a2, a2);                                      \
} while (0)

#define DO_ROW(ac, T, M, B) do {                                            \
    fma2(ac[0][0], T[0], wb[0][0][0].x); fma2(ac[0][0], T[1], wb[0][0][0].y);\
    fma2(ac[0][0], M[0], wb[0][0][1].x); fma2(ac[0][0], M[1], wb[0][0][1].y);\
    fma2(ac[0][1], T[1], wb[0][1][0].x); fma2(ac[0][1], T[2], wb[0][1][0].y);\
    fma2(ac[0][1], M[1], wb[0][1][1].x); fma2(ac[0][1], M[2], wb[0][1][1].y);\
    fma2(ac[1][0], M[0], wb[1][0][0].x); fma2(ac[1][0], M[1], wb[1][0][0].y);\
    fma2(ac[1][0], B[0], wb[1][0][1].x); fma2(ac[1][0], B[1], wb[1][0][1].y);\
    fma2(ac[1][1], M[1], wb[1][1][0].x); fma2(ac[1][1], M[2], wb[1][1][0].y);\
    fma2(ac[1][1], B[1], wb[1][1][1].x); fma2(ac[1][1], B[2], wb[1][1][1].y);\
} while (0)

    #pragma unroll 1
    for (int t = 0; t < NT; t++) {
        if (t + 1 < NT) {
            stage_tile(t + 1, (t + 1) & 1);
            cp_commit();
            cp_wait<1>();
        } else {
            cp_wait<0>();
        }
        __syncthreads();

        const float* sbuf = s_in[t & 1];

        u64 acc[RB][2][2];
        #pragma unroll
        for (int r = 0; r < RB; r++)
            #pragma unroll
            for (int py = 0; py < 2; py++)
                #pragma unroll
                for (int px = 0; px < 2; px++)
                    acc[r][py][px] = binit;

        #pragma unroll 1
        for (int ic = 0; ic < 16; ic++) {
            const int icoff = ic * (TH * TCC);
            ulonglong2 wb[2][2][2];
            #pragma unroll
            for (int py = 0; py < 2; py++)
                #pragma unroll
                for (int px = 0; px < 2; px++)
                    #pragma unroll
                    for (int ty = 0; ty < 2; ty++)
                        wb[py][px][ty] = *(const ulonglong2*)
                            &s_w[ic * 256 + py * 128 + px * 64 + ty * 32 + g * 4];

            u64 rA[3], rB[3], rC[3];
            LOAD_ROW(rA, 0);
            LOAD_ROW(rB, 1);
            LOAD_ROW(rC, 2); DO_ROW(acc[0], rA, rB, rC);
            LOAD_ROW(rA, 3); DO_ROW(acc[1], rB, rC, rA);
            LOAD_ROW(rB, 4); DO_ROW(acc[2], rC, rA, rB);
            LOAD_ROW(rC, 5); DO_ROW(acc[3], rA, rB, rC);
        }

        float* op = obase + (size_t)(2 * (iB + t * RB)) * 1024;
        #pragma unroll
        for (int r = 0; r < RB; r++) {
            #pragma unroll
            for (int py = 0; py < 2; py++) {
                float2 pe = unpack2(acc[r][py][0]);
                float2 po = unpack2(acc[r][py][1]);
                float* p = op + (size_t)(2 * r + py) * 1024;
                *(float2*)p             = make_float2(pe.x, po.x);
                *(float2*)(p + 1048576) = make_float2(pe.y, po.y);
            }
        }

        __syncthreads();   // all reads of buf (t&1) done before restage
    }
}

extern "C" void kernel_launch(void* const* d_in, const int* in_sizes, int n_in,
                              void* d_out, int out_size)
{
    const float* x    = (const float*)d_in[0];
    const float* w    = (const float*)d_in[1];
    const float* bias = (const float*)d_in[2];
    float* out        = (float*)d_out;

    build_weff_kernel<<<16, 256>>>(w);
    upconv_kernel<<<dim3(512 / TW, 512 / (RB * NT), 8), 256>>>(x, bias, out);
}

// round 11
// speedup vs baseline: 1.0365x; 1.0365x over previous
#include <cuda_runtime.h>
#include <cuda_bf16.h>
#include <cstdint>
#include <cstddef>

// SimpleUpscaleConv2d via warp-level bf16 HMMA (mma.sync.m16n8k16) implicit GEMM.
// y = conv3x3(pad=1, upsample2x_nearest(x), w*WSCALE) + bias
// x[8,16,512,512] f32 -> out[8,16,1024,1024] f32.
//
// Per input row i: D[128 px][64 n] = sum_{dy=0..2} A_dy[128][48] * B_dy[64][48]^T
//   n = oc*4 + py*2 + pxp ; k = dx*16 + ic ; A[p][k] = x[ic][i-1+dy][c0+p+dx-1]
// 3-term bf16 split: Ah*Bh + Al*Bh + Ah*Bl  (err ~2^-18 per product).
// tcgen05 unavailable (harness gencode targets plain sm_103); mma.sync is the
// baseline-PTX route to the tensor pipe.

typedef unsigned int u32;

#define A_STRIDE 112            // bytes per px row (48 bf16 = 96, pad 112: ldmatrix conflict-free)
#define A_TERM   14336          // 128*112 (one term: hi or lo)
#define A_SLOT   28672          // hi+lo
#define SM_A     0              // 4 ring slots: 114688
#define B_STRIDE 112
#define B_TERM   7168           // 64*112
#define SM_B     114688         // 6 tiles (3dy x hi/lo): 43008
#define B_BYTES  43008
#define SM_RAW   157696         // raw f32 ring: 4 slots x 16ic x 136 f32
#define RAW_SLOT 8704
#define SMEM_TOTAL 192512

__device__ __align__(16) unsigned char g_B[B_BYTES];

// ---------------------------------------------------------------------------
// PTX wrappers
// ---------------------------------------------------------------------------
static __device__ __forceinline__ void cp16z(u32 s, const void* g, u32 sz) {
    asm volatile("cp.async.cg.shared.global [%0], [%1], 16, %2;"
                 :: "r"(s), "l"(g), "r"(sz));
}
static __device__ __forceinline__ void cp16(u32 s, const void* g) {
    asm volatile("cp.async.cg.shared.global [%0], [%1], 16;" :: "r"(s), "l"(g));
}
static __device__ __forceinline__ void ldsm4(u32 a, u32& r0, u32& r1, u32& r2, u32& r3) {
    asm volatile("ldmatrix.sync.aligned.m8n8.x4.shared.b16 {%0,%1,%2,%3}, [%4];"
                 : "=r"(r0), "=r"(r1), "=r"(r2), "=r"(r3) : "r"(a));
}
static __device__ __forceinline__ void mma16816(float* d, u32 a0, u32 a1, u32 a2, u32 a3,
                                                u32 b0, u32 b1) {
    asm volatile("mma.sync.aligned.m16n8k16.row.col.f32.bf16.bf16.f32 "
                 "{%0,%1,%2,%3}, {%4,%5,%6,%7}, {%8,%9}, {%0,%1,%2,%3};"
                 : "+f"(d[0]), "+f"(d[1]), "+f"(d[2]), "+f"(d[3])
                 : "r"(a0), "r"(a1), "r"(a2), "r"(a3), "r"(b0), "r"(b1));
}

// ---------------------------------------------------------------------------
// Pre-kernel: B_dy[term][n][k] bf16 (hi & residual lo), parity-combined,
// wscale-folded.  Row tap sets (verified against the proven R1 combination):
//   py=0: dy0->{ky0}, dy1->{ky1,ky2}; py=1: dy1->{ky0,ky1}, dy2->{ky2}; else empty
// (same for pxp/dx with kx).
// ---------------------------------------------------------------------------
__global__ void build_B_kernel(const float* __restrict__ w) {
    int idx = blockIdx.x * 256 + threadIdx.x;    // 9216 = 3dy*2term*64n*24kpair
    if (idx >= 9216) return;
    int kp   = idx % 24;
    int n    = (idx / 24) % 64;
    int term = (idx / (24 * 64)) % 2;
    int dy   = idx / (24 * 64 * 2);
    int pxp = n & 1, py = (n >> 1) & 1, oc = n >> 2;
    const float WS = (float)(1.4142135623730951 / 12.0);  // sqrt(2)/sqrt(16*9)

    unsigned short hv[2];
    #pragma unroll
    for (int q = 0; q < 2; q++) {
        int k = 2 * kp + q, dx = k >> 4, ic = k & 15;
        int ylo = 1, yhi = 0, xlo = 1, xhi = 0;   // empty by default
        if (py == 0) { if (dy == 0) { ylo = 0; yhi = 0; } else if (dy == 1) { ylo = 1; yhi = 2; } }
        else         { if (dy == 1) { ylo = 0; yhi = 1; } else if (dy == 2) { ylo = 2; yhi = 2; } }
        if (pxp == 0){ if (dx == 0) { xlo = 0; xhi = 0; } else if (dx == 1) { xlo = 1; xhi = 2; } }
        else         { if (dx == 1) { xlo = 0; xhi = 1; } else if (dx == 2) { xlo = 2; xhi = 2; } }
        float s = 0.f;
        for (int ky = ylo; ky <= yhi; ky++)
            for (int kx = xlo; kx <= xhi; kx++)
                s += w[((oc * 16 + ic) * 3 + ky) * 3 + kx];
        s *= WS;
        __nv_bfloat16 hi = __float2bfloat16(s);
        hv[q] = (term == 0) ? __bfloat16_as_ushort(hi)
              : __bfloat16_as_ushort(__float2bfloat16(s - __bfloat162float(hi)));
    }
    u32 packed = ((u32)hv[1] << 16) | hv[0];
    *(u32*)(g_B + (dy * 2 + term) * B_TERM + n * B_STRIDE + kp * 4) = packed;
}

// ---------------------------------------------------------------------------
// Staging: raw f32 row (cols [c0-4, c0+132), 34 aligned 16B chunks x 16 ic)
// ---------------------------------------------------------------------------
static __device__ __forceinline__ void stage_raw(u32 sb, const float* __restrict__ xb,
                                                 int c0, int r, int tid) {
    bool rok = ((unsigned)r < 512u);
    u32 dst0 = sb + SM_RAW + (u32)(r & 3) * RAW_SLOT;
    #pragma unroll
    for (int it = 0; it < 3; it++) {
        int idx = tid + it * 256;
        if (idx >= 544) break;
        int ic = idx / 34, ch = idx - ic * 34;
        int colb = c0 - 4 + ch * 4;                   // multiple of 4; chunks all-valid or all-invalid
        bool ok = rok && ((unsigned)colb < 512u);
        const float* src = ok ? (xb + (size_t)ic * 262144 + (size_t)r * 512 + colb) : xb;
        cp16z(dst0 + (u32)(ic * 544 + ch * 16), src, ok ? 16u : 0u);
    }
}

// Convert raw row -> A slot (split bf16 hi/lo), k = dx*16+ic, rows p stride 112B
static __device__ __forceinline__ void convert_row(char* smem, int r, int tid) {
    int p   = tid & 127;
    int ic0 = (tid >> 7) * 8;
    const float* raw = (const float*)(smem + SM_RAW + (size_t)(r & 3) * RAW_SLOT);
    char* ahi = smem + SM_A + (size_t)(r & 3) * A_SLOT;
    #pragma unroll
    for (int pr = 0; pr < 4; pr++) {
        int ica = ic0 + 2 * pr;
        const float* ra = raw + ica * 136;
        const float* rb = raw + (ica + 1) * 136;
        #pragma unroll
        for (int d = 0; d < 3; d++) {
            float fa = ra[p + 3 + d], fb = rb[p + 3 + d];
            __nv_bfloat16 ha = __float2bfloat16(fa), hb = __float2bfloat16(fb);
            __nv_bfloat16 la = __float2bfloat16(fa - __bfloat162float(ha));
            __nv_bfloat16 lb = __float2bfloat16(fb - __bfloat162float(hb));
            u32 hp = ((u32)__bfloat16_as_ushort(hb) << 16) | __bfloat16_as_ushort(ha);
            u32 lp = ((u32)__bfloat16_as_ushort(lb) << 16) | __bfloat16_as_ushort(la);
            int off = p * A_STRIDE + (d * 16 + ica) * 2;
            *(u32*)(ahi + off)          = hp;
            *(u32*)(ahi + A_TERM + off) = lp;
        }
    }
}

// ---------------------------------------------------------------------------
// Main kernel: 256 threads = 8 warps; warp w -> px rows [16w,16w+16), all 64 n.
// ---------------------------------------------------------------------------
__global__ void __launch_bounds__(256) upconv_hmma(
    const float* __restrict__ x,
    const float* __restrict__ bias,
    float* __restrict__ out)
{
    extern __shared__ __align__(128) char smem[];
    const int tid = threadIdx.x, lane = tid & 31, wid = tid >> 5;
    const int c0 = blockIdx.x * 128, i0 = blockIdx.y * 16, nb = blockIdx.z;
    const float* xb = x + (size_t)nb * 16 * 262144;
    float* outb     = out + (size_t)nb * 16 * 1048576;
    u32 sb = (u32)__cvta_generic_to_shared(smem);

    // stage B tiles + raw rows i0-1..i0+2, one group
    for (int k2 = tid; k2 < B_BYTES / 16; k2 += 256)
        cp16(sb + SM_B + k2 * 16, g_B + k2 * 16);
    stage_raw(sb, xb, c0, i0 - 1, tid);
    stage_raw(sb, xb, c0, i0,     tid);
    stage_raw(sb, xb, c0, i0 + 1, tid);
    stage_raw(sb, xb, c0, i0 + 2, tid);
    asm volatile("cp.async.commit_group;" ::: "memory");
    asm volatile("cp.async.wait_group 0;" ::: "memory");
    __syncthreads();
    convert_row(smem, i0 - 1, tid);
    convert_row(smem, i0,     tid);
    convert_row(smem, i0 + 1, tid);
    __syncthreads();

    // per-thread fragment address offsets (ldmatrix x4 layout)
    const u32 a_loff = (u32)((16 * wid + (lane & 7) + ((lane >> 3) & 1) * 8) * A_STRIDE
                             + (lane >> 4) * 16);
    const u32 b_loff = (u32)(((lane & 7) + ((lane >> 3) & 1) * 8) * B_STRIDE
                             + (lane >> 4) * 16);
    float bvv[8];
    #pragma unroll
    for (int nt = 0; nt < 8; nt++) bvv[nt] = bias[2 * nt + ((lane & 3) >> 1)];

    #pragma unroll 1
    for (int i = i0; i < i0 + 16; i++) {
        float acc[8][4];
        #pragma unroll
        for (int nt = 0; nt < 8; nt++)
            #pragma unroll
            for (int j = 0; j < 4; j++) acc[nt][j] = bvv[nt];

        #pragma unroll
        for (int dy = 0; dy < 3; dy++) {
            u32 abase = sb + SM_A + (u32)((i - 1 + dy) & 3) * A_SLOT + a_loff;
            u32 bbase = sb + SM_B + (u32)(dy * 2) * B_TERM + b_loff;
            #pragma unroll
            for (int ks = 0; ks < 3; ks++) {
                u32 ah0, ah1, ah2, ah3, al0, al1, al2, al3;
                ldsm4(abase + ks * 32,          ah0, ah1, ah2, ah3);
                ldsm4(abase + ks * 32 + A_TERM, al0, al1, al2, al3);
                #pragma unroll
                for (int np = 0; np < 4; np++) {
                    u32 ba = bbase + (u32)(np * 16 * B_STRIDE) + ks * 32;
                    u32 h0, h1, h2, h3, l0, l1, l2, l3;
                    ldsm4(ba,          h0, h1, h2, h3);
                    ldsm4(ba + B_TERM, l0, l1, l2, l3);
                    // interleave the two acc chains for ILP
                    mma16816(acc[2 * np],     ah0, ah1, ah2, ah3, h0, h2);
                    mma16816(acc[2 * np + 1], ah0, ah1, ah2, ah3, h1, h3);
                    mma16816(acc[2 * np],     al0, al1, al2, al3, h0, h2);
                    mma16816(acc[2 * np + 1], al0, al1, al2, al3, h1, h3);
                    mma16816(acc[2 * np],     ah0, ah1, ah2, ah3, l0, l2);
                    mma16816(acc[2 * np + 1], ah0, ah1, ah2, ah3, l1, l3);
                }
            }
        }

        // epilogue: d0/d1 -> cols 2(c0+m)+{0,1}, d2/d3 -> m+8
        {
            int colf = 2 * (c0 + 16 * wid + (lane >> 2));
            #pragma unroll
            for (int nt = 0; nt < 8; nt++) {
                int n0 = 8 * nt + 2 * (lane & 3);
                int oc = n0 >> 2, py = (n0 >> 1) & 1;
                float* p = outb + (size_t)oc * 1048576 + (size_t)(2 * i + py) * 1024 + colf;
                *(float2*)p        = make_float2(acc[nt][0], acc[nt][1]);
                *(float2*)(p + 16) = make_float2(acc[nt][2], acc[nt][3]);
            }
        }

        __syncthreads();                              // all mma reads of slot (i+2)&3's old row done
        asm volatile("cp.async.wait_group 0;" ::: "memory");   // raw(i+2) arrived
        if (i + 2 <= i0 + 16) convert_row(smem, i + 2, tid);
        if (i + 3 <= i0 + 16) {
            stage_raw(sb, xb, c0, i + 3, tid);
            asm volatile("cp.async.commit_group;" ::: "memory");
        }
        __syncthreads();                              // converted A visible next step
    }
}

extern "C" void kernel_launch(void* const* d_in, const int* in_sizes, int n_in,
                              void* d_out, int out_size)
{
    const float* x    = (const float*)d_in[0];
    const float* w    = (const float*)d_in[1];
    const float* bias = (const float*)d_in[2];
    float* out        = (float*)d_out;

    cudaFuncSetAttribute(upconv_hmma,
                         cudaFuncAttributeMaxDynamicSharedMemorySize, SMEM_TOTAL);

    build_B_kernel<<<36, 256>>>(w);
    upconv_hmma<<<dim3(4, 32, 8), 256, SMEM_TOTAL>>>(x, bias, out);
}

// round 16
// speedup vs baseline: 1.4109x; 1.3613x over previous
#include <cuda_runtime.h>
#include <cuda_bf16.h>
#include <cstdint>
#include <cstddef>

// SimpleUpscaleConv2d via warp-level bf16 HMMA, parity-factorized implicit GEMM.
// y = conv3x3(pad=1, upsample2x_nearest(x), w*WSCALE) + bias
// x[8,16,512,512] f32 -> out[8,16,1024,1024] f32.
//
// Per input row i and output parity (py,px):
//   D[128 px][16 oc] = A[128][64] * B[py][px][16][64]^T
//   k = wy*32 + c*16 + ic  (2x2 input window per parity)
// 3-term bf16 split (AhBh + AlBh + AhBl), rel err ~1e-5.
// Warp-private pipeline, no __syncthreads in the steady loop.
// R14 fix: prologue issued two cp.async groups to the SAME raw slot with no
// intervening wait (rows i0-1 and i0+1 -> slot (i0-1)&1); inter-group cp.async
// writes to one address are unordered -> nondeterministic A(i0+1). Prologue
// now stages each slot exactly once between waits.

typedef unsigned int u32;

#define A_STRIDE 112
#define A_TERM   1792            // 16 px * 112
#define A_SLOT   3584            // hi + lo
#define A_WARP   14336           // 4 ring slots
#define SM_A     0               // 8 warps: 114688
#define RAW_SLOT 1536            // 16 ic * 24 f32
#define RAW_WARP 3072            // ring of 2
#define SM_RAW   114688          // total 24576
#define SM_B     139264
#define B_REGION 2304            // 16 oc rows * 144B
#define B_BYTES  18432           // 8 regions (py,px,term)
#define SMEM_TOTAL 157696

__device__ __align__(16) unsigned char g_B[B_BYTES];

static __device__ __forceinline__ void cp16z(u32 s, const void* g, u32 sz) {
    asm volatile("cp.async.cg.shared.global [%0], [%1], 16, %2;"
                 :: "r"(s), "l"(g), "r"(sz));
}
static __device__ __forceinline__ void cp16(u32 s, const void* g) {
    asm volatile("cp.async.cg.shared.global [%0], [%1], 16;" :: "r"(s), "l"(g));
}
static __device__ __forceinline__ void ldsm4(u32 a, u32& r0, u32& r1, u32& r2, u32& r3) {
    asm volatile("ldmatrix.sync.aligned.m8n8.x4.shared.b16 {%0,%1,%2,%3}, [%4];"
                 : "=r"(r0), "=r"(r1), "=r"(r2), "=r"(r3) : "r"(a));
}
static __device__ __forceinline__ void mma16816(float* d, const u32* a, u32 b0, u32 b1) {
    asm volatile("mma.sync.aligned.m16n8k16.row.col.f32.bf16.bf16.f32 "
                 "{%0,%1,%2,%3}, {%4,%5,%6,%7}, {%8,%9}, {%0,%1,%2,%3};"
                 : "+f"(d[0]), "+f"(d[1]), "+f"(d[2]), "+f"(d[3])
                 : "r"(a[0]), "r"(a[1]), "r"(a[2]), "r"(a[3]), "r"(b0), "r"(b1));
}

// ---------------------------------------------------------------------------
// Pre-kernel: B[py][px][term][oc][k], k = wy*32 + c*16 + ic.
//   py=0: wy0 -> ky{0}, wy1 -> ky{1,2};  py=1: wy0 -> ky{0,1}, wy1 -> ky{2}
//   px=0: c0  -> kx{0}, c1  -> kx{1,2};  px=1: c0  -> kx{0,1}, c1  -> kx{2}
// ---------------------------------------------------------------------------
__global__ void build_B_kernel(const float* __restrict__ w) {
    int idx = blockIdx.x * 256 + threadIdx.x;   // 4096 = 8 regions * 16 oc * 32 kpair
    if (idx >= 4096) return;
    int kp = idx & 31;
    int oc = (idx >> 5) & 15;
    int region = idx >> 9;                      // ((py*2+px)*2+term)
    int term = region & 1, px = (region >> 1) & 1, py = region >> 2;
    const float WS = (float)(1.4142135623730951 / 12.0);  // sqrt(2)/sqrt(16*9)

    unsigned short hv[2];
    #pragma unroll
    for (int q = 0; q < 2; q++) {
        int k = 2 * kp + q;
        int wy = k >> 5, c = (k >> 4) & 1, ic = k & 15;
        int ylo, yhi, xlo, xhi;
        if (py == 0) { if (wy == 0) { ylo = 0; yhi = 0; } else { ylo = 1; yhi = 2; } }
        else         { if (wy == 0) { ylo = 0; yhi = 1; } else { ylo = 2; yhi = 2; } }
        if (px == 0) { if (c == 0)  { xlo = 0; xhi = 0; } else { xlo = 1; xhi = 2; } }
        else         { if (c == 0)  { xlo = 0; xhi = 1; } else { xlo = 2; xhi = 2; } }
        float s = 0.f;
        for (int ky = ylo; ky <= yhi; ky++)
            for (int kx = xlo; kx <= xhi; kx++)
                s += w[((oc * 16 + ic) * 3 + ky) * 3 + kx];
        s *= WS;
        __nv_bfloat16 hi = __float2bfloat16(s);
        hv[q] = (term == 0) ? __bfloat16_as_ushort(hi)
              : __bfloat16_as_ushort(__float2bfloat16(s - __bfloat162float(hi)));
    }
    *(u32*)(g_B + region * B_REGION + oc * 144 + kp * 4) = ((u32)hv[1] << 16) | hv[0];
}

// ---------------------------------------------------------------------------
// Warp-private staging: raw f32 cols [cw-4, cw+20) x 16 ic for row r.
// ---------------------------------------------------------------------------
static __device__ __forceinline__ void stage_raw_warp(u32 rwb, const float* __restrict__ xb,
                                                      int cw, int r, int lane) {
    bool rok = ((unsigned)r < 512u);
    u32 dst = rwb + (u32)(r & 1) * RAW_SLOT;
    #pragma unroll
    for (int it = 0; it < 3; it++) {
        int idx = lane + it * 32;                 // 0..95 = 16 ic x 6 chunks
        int ic = idx / 6, ch = idx - ic * 6;
        int cb = cw - 4 + ch * 4;
        bool ok = rok && ((unsigned)cb < 509u);   // whole-chunk validity
        const float* src = ok ? xb + (size_t)ic * 262144 + (size_t)r * 512 + cb : xb;
        cp16z(dst + (u32)(ic * 96 + ch * 16), src, ok ? 16u : 0u);
    }
}

// Warp-private convert: raw row r -> A slot (split bf16 hi/lo), k=(d,ic).
static __device__ __forceinline__ void convert_warp(char* smem, int wid, int lane, int r) {
    const float* raw = (const float*)(smem + SM_RAW + wid * RAW_WARP + (r & 1) * RAW_SLOT);
    char* A = smem + SM_A + wid * A_WARP + (r & 3) * A_SLOT;
    int p = lane & 15, h = lane >> 4;
    #pragma unroll
    for (int d = 0; d < 3; d++)
        #pragma unroll
        for (int icp = 0; icp < 4; icp++) {
            int ic = h * 8 + icp * 2;
            float fa = raw[ic * 24 + p + d + 3];
            float fb = raw[(ic + 1) * 24 + p + d + 3];
            __nv_bfloat16 ha = __float2bfloat16(fa), hb = __float2bfloat16(fb);
            __nv_bfloat16 la = __float2bfloat16(fa - __bfloat162float(ha));
            __nv_bfloat16 lb = __float2bfloat16(fb - __bfloat162float(hb));
            u32 hp = ((u32)__bfloat16_as_ushort(hb) << 16) | __bfloat16_as_ushort(ha);
            u32 lp = ((u32)__bfloat16_as_ushort(lb) << 16) | __bfloat16_as_ushort(la);
            int off = p * A_STRIDE + (d * 16 + ic) * 2;
            *(u32*)(A + off)          = hp;
            *(u32*)(A + A_TERM + off) = lp;
        }
}

// ---------------------------------------------------------------------------
// Main kernel: 256 threads = 8 warps; warp w owns px cols [16w, 16w+16).
// ---------------------------------------------------------------------------
__global__ void __launch_bounds__(256) upconv_hmma2(
    const float* __restrict__ x,
    const float* __restrict__ bias,
    float* __restrict__ out)
{
    extern __shared__ __align__(128) char smem[];
    const int tid = threadIdx.x, lane = tid & 31, wid = tid >> 5;
    const int c0 = blockIdx.x * 128, i0 = blockIdx.y * 16, nb = blockIdx.z;
    const int cw = c0 + 16 * wid;
    const float* xb = x + (size_t)nb * 16 * 262144;
    float* outb     = out + (size_t)nb * 16 * 1048576;
    u32 sb = (u32)__cvta_generic_to_shared(smem);
    const u32 awb = sb + SM_A + wid * A_WARP;
    const u32 rwb = sb + SM_RAW + wid * RAW_WARP;

    // ---- prologue: each raw slot staged exactly once between waits ----
    for (int k2 = tid; k2 < B_BYTES / 16; k2 += 256)
        cp16(sb + SM_B + k2 * 16, g_B + k2 * 16);
    stage_raw_warp(rwb, xb, cw, i0 - 1, lane);           // slot (i0-1)&1
    stage_raw_warp(rwb, xb, cw, i0, lane);               // slot i0&1  (distinct)
    asm volatile("cp.async.commit_group;" ::: "memory");
    asm volatile("cp.async.wait_group 0;" ::: "memory"); // B + both rows landed
    __syncthreads();                                     // B visible to all warps
    convert_warp(smem, wid, lane, i0 - 1);
    convert_warp(smem, wid, lane, i0);
    stage_raw_warp(rwb, xb, cw, i0 + 1, lane);           // slot (i0-1)&1, now free
    asm volatile("cp.async.commit_group;" ::: "memory");
    asm volatile("cp.async.wait_group 0;" ::: "memory");
    convert_warp(smem, wid, lane, i0 + 1);
    stage_raw_warp(rwb, xb, cw, i0 + 2, lane);           // slot i0&1, now free
    asm volatile("cp.async.commit_group;" ::: "memory");
    __syncwarp();
    // loop entry: A rows i0-1..i0+1 converted; raw(i0+2) in flight (1 group)

    const u32 a_lane = (u32)((lane & 15) * A_STRIDE + (lane >> 4) * 16);
    const u32 b_lane = sb + SM_B + (u32)((lane & 15) * 144 + (lane >> 4) * 16);
    float bv[2][2];
    #pragma unroll
    for (int nh = 0; nh < 2; nh++)
        #pragma unroll
        for (int u = 0; u < 2; u++)
            bv[nh][u] = bias[2 * (lane & 3) + 8 * nh + u];

    #pragma unroll 1
    for (int i = i0; i < i0 + 16; i++) {
        float acc[2][2][2][4];            // [py][pxp][nh][frag]
        #pragma unroll
        for (int py = 0; py < 2; py++)
            #pragma unroll
            for (int px = 0; px < 2; px++)
                #pragma unroll
                for (int nh = 0; nh < 2; nh++)
                    #pragma unroll
                    for (int j = 0; j < 4; j++)
                        acc[py][px][nh][j] = bv[nh][j & 1];

        #pragma unroll
        for (int py = 0; py < 2; py++) {
            // A fragments for the two window rows of this py: rows i-1+py, i+py
            u32 fA[2][3][2][4];
            #pragma unroll
            for (int wy = 0; wy < 2; wy++) {
                u32 ab = awb + (u32)((i - 1 + py + wy) & 3) * A_SLOT + a_lane;
                #pragma unroll
                for (int d = 0; d < 3; d++)
                    #pragma unroll
                    for (int t = 0; t < 2; t++)
                        ldsm4(ab + d * 32 + t * A_TERM,
                              fA[wy][d][t][0], fA[wy][d][t][1],
                              fA[wy][d][t][2], fA[wy][d][t][3]);
            }
            #pragma unroll
            for (int px = 0; px < 2; px++) {
                u32 bH = b_lane + (u32)(((py * 2 + px) * 2 + 0) * B_REGION);
                u32 bL = bH + B_REGION;
                #pragma unroll
                for (int ks = 0; ks < 4; ks++) {
                    int wy = ks >> 1, dxx = px + (ks & 1);
                    u32 h0, h1, h2, h3, l0, l1, l2, l3;
                    ldsm4(bH + ks * 32, h0, h1, h2, h3);
                    ldsm4(bL + ks * 32, l0, l1, l2, l3);
                    const u32* aH = fA[wy][dxx][0];
                    const u32* aL = fA[wy][dxx][1];
                    mma16816(acc[py][px][0], aH, h0, h2);
                    mma16816(acc[py][px][1], aH, h1, h3);
                    mma16816(acc[py][px][0], aL, h0, h2);
                    mma16816(acc[py][px][1], aL, h1, h3);
                    mma16816(acc[py][px][0], aH, l0, l2);
                    mma16816(acc[py][px][1], aH, l1, l3);
                }
            }
        }

        // epilogue (warp-private, coalesced float2: px parities -> adjacent cols)
        {
            int q = lane >> 2;
            #pragma unroll
            for (int py = 0; py < 2; py++)
                #pragma unroll
                for (int nh = 0; nh < 2; nh++)
                    #pragma unroll
                    for (int j = 0; j < 4; j++) {
                        int p  = (j >= 2) ? q + 8 : q;
                        int oc = 2 * (lane & 3) + 8 * nh + (j & 1);
                        float* ptr = outb + (size_t)oc * 1048576
                                   + (size_t)(2 * i + py) * 1024 + 2 * (cw + p);
                        *(float2*)ptr = make_float2(acc[py][0][nh][j], acc[py][1][nh][j]);
                    }
        }

        // advance pipeline (warp-private; no block sync)
        asm volatile("cp.async.wait_group 0;" ::: "memory");   // raw(i+2) arrived
        if (i + 2 <= i0 + 16) convert_warp(smem, wid, lane, i + 2);
        __syncwarp();
        if (i + 3 <= i0 + 16) {
            stage_raw_warp(rwb, xb, cw, i + 3, lane);
            asm volatile("cp.async.commit_group;" ::: "memory");
        }
    }
}

extern "C" void kernel_launch(void* const* d_in, const int* in_sizes, int n_in,
                              void* d_out, int out_size)
{
    const float* x    = (const float*)d_in[0];
    const float* w    = (const float*)d_in[1];
    const float* bias = (const float*)d_in[2];
    float* out        = (float*)d_out;

    cudaFuncSetAttribute(upconv_hmma2,
                         cudaFuncAttributeMaxDynamicSharedMemorySize, SMEM_TOTAL);

    build_B_kernel<<<16, 256>>>(w);
    upconv_hmma2<<<dim3(4, 32, 8), 256, SMEM_TOTAL>>>(x, bias, out);
}

// round 17
// speedup vs baseline: 1.5328x; 1.0864x over previous
#include <cuda_runtime.h>
#include <cuda_bf16.h>
#include <cstdint>
#include <cstddef>

// SimpleUpscaleConv2d via warp-level bf16 HMMA, parity-factorized implicit GEMM.
// y = conv3x3(pad=1, upsample2x_nearest(x), w*WSCALE) + bias
// x[8,16,512,512] f32 -> out[8,16,1024,1024] f32.
//
// Per input row i and output parity (py,px):
//   D[128 px][16 oc] = A[128][64] * B[py][px][16][64]^T
// 3-term bf16 split (AhBh + AlBh + AhBl), rel err ~1e-5.
// R16: ncu showed L1=80.4% (smem-wavefront bound), tensor only 30%. 32 of 56
// ldsm4 per step reloaded loop-invariant B. This round hoists ALL B fragments
// into 128 registers once per block (occupancy is smem-limited at 1 block/SM,
// so registers are free up to 256/thread) -> 24 ldsm4 per step.

typedef unsigned int u32;

#define A_STRIDE 112
#define A_TERM   1792            // 16 px * 112
#define A_SLOT   3584            // hi + lo
#define A_WARP   14336           // 4 ring slots
#define SM_A     0               // 8 warps: 114688
#define RAW_SLOT 1536            // 16 ic * 24 f32
#define RAW_WARP 3072            // ring of 2
#define SM_RAW   114688          // total 24576
#define SM_B     139264
#define B_REGION 2304            // 16 oc rows * 144B
#define B_BYTES  18432           // 8 regions (py,px,term)
#define SMEM_TOTAL 157696

__device__ __align__(16) unsigned char g_B[B_BYTES];

static __device__ __forceinline__ void cp16z(u32 s, const void* g, u32 sz) {
    asm volatile("cp.async.cg.shared.global [%0], [%1], 16, %2;"
                 :: "r"(s), "l"(g), "r"(sz));
}
static __device__ __forceinline__ void cp16(u32 s, const void* g) {
    asm volatile("cp.async.cg.shared.global [%0], [%1], 16;" :: "r"(s), "l"(g));
}
static __device__ __forceinline__ void ldsm4(u32 a, u32& r0, u32& r1, u32& r2, u32& r3) {
    asm volatile("ldmatrix.sync.aligned.m8n8.x4.shared.b16 {%0,%1,%2,%3}, [%4];"
                 : "=r"(r0), "=r"(r1), "=r"(r2), "=r"(r3) : "r"(a));
}
static __device__ __forceinline__ void mma16816(float* d, const u32* a, u32 b0, u32 b1) {
    asm volatile("mma.sync.aligned.m16n8k16.row.col.f32.bf16.bf16.f32 "
                 "{%0,%1,%2,%3}, {%4,%5,%6,%7}, {%8,%9}, {%0,%1,%2,%3};"
                 : "+f"(d[0]), "+f"(d[1]), "+f"(d[2]), "+f"(d[3])
                 : "r"(a[0]), "r"(a[1]), "r"(a[2]), "r"(a[3]), "r"(b0), "r"(b1));
}

// ---------------------------------------------------------------------------
// Pre-kernel: B[py][px][term][oc][k], k = wy*32 + c*16 + ic.
//   py=0: wy0 -> ky{0}, wy1 -> ky{1,2};  py=1: wy0 -> ky{0,1}, wy1 -> ky{2}
//   px=0: c0  -> kx{0}, c1  -> kx{1,2};  px=1: c0  -> kx{0,1}, c1  -> kx{2}
// ---------------------------------------------------------------------------
__global__ void build_B_kernel(const float* __restrict__ w) {
    int idx = blockIdx.x * 256 + threadIdx.x;   // 4096 = 8 regions * 16 oc * 32 kpair
    if (idx >= 4096) return;
    int kp = idx & 31;
    int oc = (idx >> 5) & 15;
    int region = idx >> 9;                      // ((py*2+px)*2+term)
    int term = region & 1, px = (region >> 1) & 1, py = region >> 2;
    const float WS = (float)(1.4142135623730951 / 12.0);  // sqrt(2)/sqrt(16*9)

    unsigned short hv[2];
    #pragma unroll
    for (int q = 0; q < 2; q++) {
        int k = 2 * kp + q;
        int wy = k >> 5, c = (k >> 4) & 1, ic = k & 15;
        int ylo, yhi, xlo, xhi;
        if (py == 0) { if (wy == 0) { ylo = 0; yhi = 0; } else { ylo = 1; yhi = 2; } }
        else         { if (wy == 0) { ylo = 0; yhi = 1; } else { ylo = 2; yhi = 2; } }
        if (px == 0) { if (c == 0)  { xlo = 0; xhi = 0; } else { xlo = 1; xhi = 2; } }
        else         { if (c == 0)  { xlo = 0; xhi = 1; } else { xlo = 2; xhi = 2; } }
        float s = 0.f;
        for (int ky = ylo; ky <= yhi; ky++)
            for (int kx = xlo; kx <= xhi; kx++)
                s += w[((oc * 16 + ic) * 3 + ky) * 3 + kx];
        s *= WS;
        __nv_bfloat16 hi = __float2bfloat16(s);
        hv[q] = (term == 0) ? __bfloat16_as_ushort(hi)
              : __bfloat16_as_ushort(__float2bfloat16(s - __bfloat162float(hi)));
    }
    *(u32*)(g_B + region * B_REGION + oc * 144 + kp * 4) = ((u32)hv[1] << 16) | hv[0];
}

// ---------------------------------------------------------------------------
// Warp-private staging: raw f32 cols [cw-4, cw+20) x 16 ic for row r.
// ---------------------------------------------------------------------------
static __device__ __forceinline__ void stage_raw_warp(u32 rwb, const float* __restrict__ xb,
                                                      int cw, int r, int lane) {
    bool rok = ((unsigned)r < 512u);
    u32 dst = rwb + (u32)(r & 1) * RAW_SLOT;
    #pragma unroll
    for (int it = 0; it < 3; it++) {
        int idx = lane + it * 32;                 // 0..95 = 16 ic x 6 chunks
        int ic = idx / 6, ch = idx - ic * 6;
        int cb = cw - 4 + ch * 4;
        bool ok = rok && ((unsigned)cb < 509u);   // whole-chunk validity
        const float* src = ok ? xb + (size_t)ic * 262144 + (size_t)r * 512 + cb : xb;
        cp16z(dst + (u32)(ic * 96 + ch * 16), src, ok ? 16u : 0u);
    }
}

// Warp-private convert: raw row r -> A slot (split bf16 hi/lo), k=(d,ic).
static __device__ __forceinline__ void convert_warp(char* smem, int wid, int lane, int r) {
    const float* raw = (const float*)(smem + SM_RAW + wid * RAW_WARP + (r & 1) * RAW_SLOT);
    char* A = smem + SM_A + wid * A_WARP + (r & 3) * A_SLOT;
    int p = lane & 15, h = lane >> 4;
    #pragma unroll
    for (int d = 0; d < 3; d++)
        #pragma unroll
        for (int icp = 0; icp < 4; icp++) {
            int ic = h * 8 + icp * 2;
            float fa = raw[ic * 24 + p + d + 3];
            float fb = raw[(ic + 1) * 24 + p + d + 3];
            __nv_bfloat16 ha = __float2bfloat16(fa), hb = __float2bfloat16(fb);
            __nv_bfloat16 la = __float2bfloat16(fa - __bfloat162float(ha));
            __nv_bfloat16 lb = __float2bfloat16(fb - __bfloat162float(hb));
            u32 hp = ((u32)__bfloat16_as_ushort(hb) << 16) | __bfloat16_as_ushort(ha);
            u32 lp = ((u32)__bfloat16_as_ushort(lb) << 16) | __bfloat16_as_ushort(la);
            int off = p * A_STRIDE + (d * 16 + ic) * 2;
            *(u32*)(A + off)          = hp;
            *(u32*)(A + A_TERM + off) = lp;
        }
}

// ---------------------------------------------------------------------------
// Main kernel: 256 threads = 8 warps; warp w owns px cols [16w, 16w+16).
// ---------------------------------------------------------------------------
__global__ void __launch_bounds__(256) upconv_hmma2(
    const float* __restrict__ x,
    const float* __restrict__ bias,
    float* __restrict__ out)
{
    extern __shared__ __align__(128) char smem[];
    const int tid = threadIdx.x, lane = tid & 31, wid = tid >> 5;
    const int c0 = blockIdx.x * 128, i0 = blockIdx.y * 16, nb = blockIdx.z;
    const int cw = c0 + 16 * wid;
    const float* xb = x + (size_t)nb * 16 * 262144;
    float* outb     = out + (size_t)nb * 16 * 1048576;
    u32 sb = (u32)__cvta_generic_to_shared(smem);
    const u32 awb = sb + SM_A + wid * A_WARP;
    const u32 rwb = sb + SM_RAW + wid * RAW_WARP;

    // ---- prologue: each raw slot staged exactly once between waits ----
    for (int k2 = tid; k2 < B_BYTES / 16; k2 += 256)
        cp16(sb + SM_B + k2 * 16, g_B + k2 * 16);
    stage_raw_warp(rwb, xb, cw, i0 - 1, lane);           // slot (i0-1)&1
    stage_raw_warp(rwb, xb, cw, i0, lane);               // slot i0&1  (distinct)
    asm volatile("cp.async.commit_group;" ::: "memory");
    asm volatile("cp.async.wait_group 0;" ::: "memory"); // B + both rows landed
    __syncthreads();                                     // B visible to all warps
    convert_warp(smem, wid, lane, i0 - 1);
    convert_warp(smem, wid, lane, i0);
    stage_raw_warp(rwb, xb, cw, i0 + 1, lane);           // slot (i0-1)&1, now free
    asm volatile("cp.async.commit_group;" ::: "memory");
    asm volatile("cp.async.wait_group 0;" ::: "memory");
    convert_warp(smem, wid, lane, i0 + 1);
    stage_raw_warp(rwb, xb, cw, i0 + 2, lane);           // slot i0&1, now free
    asm volatile("cp.async.commit_group;" ::: "memory");
    __syncwarp();
    // loop entry: A rows i0-1..i0+1 converted; raw(i0+2) in flight (1 group)

    const u32 a_lane = (u32)((lane & 15) * A_STRIDE + (lane >> 4) * 16);
    const u32 b_lane = sb + SM_B + (u32)((lane & 15) * 144 + (lane >> 4) * 16);

    // ---- hoist ALL B fragments into registers (loop-invariant, 128 u32) ----
    u32 fB[2][2][2][4][4];     // [py][px][term][ks][reg]
    #pragma unroll
    for (int py = 0; py < 2; py++)
        #pragma unroll
        for (int px = 0; px < 2; px++)
            #pragma unroll
            for (int t = 0; t < 2; t++) {
                u32 bA = b_lane + (u32)((((py * 2 + px) * 2 + t)) * B_REGION);
                #pragma unroll
                for (int ks = 0; ks < 4; ks++)
                    ldsm4(bA + ks * 32, fB[py][px][t][ks][0], fB[py][px][t][ks][1],
                          fB[py][px][t][ks][2], fB[py][px][t][ks][3]);
            }

    float bv[2][2];
    #pragma unroll
    for (int nh = 0; nh < 2; nh++)
        #pragma unroll
        for (int u = 0; u < 2; u++)
            bv[nh][u] = bias[2 * (lane & 3) + 8 * nh + u];

    #pragma unroll 1
    for (int i = i0; i < i0 + 16; i++) {
        float acc[2][2][2][4];            // [py][pxp][nh][frag]
        #pragma unroll
        for (int py = 0; py < 2; py++)
            #pragma unroll
            for (int px = 0; px < 2; px++)
                #pragma unroll
                for (int nh = 0; nh < 2; nh++)
                    #pragma unroll
                    for (int j = 0; j < 4; j++)
                        acc[py][px][nh][j] = bv[nh][j & 1];

        #pragma unroll
        for (int py = 0; py < 2; py++) {
            // A fragments for the two window rows of this py: rows i-1+py, i+py
            u32 fA[2][3][2][4];
            #pragma unroll
            for (int wy = 0; wy < 2; wy++) {
                u32 ab = awb + (u32)((i - 1 + py + wy) & 3) * A_SLOT + a_lane;
                #pragma unroll
                for (int d = 0; d < 3; d++)
                    #pragma unroll
                    for (int t = 0; t < 2; t++)
                        ldsm4(ab + d * 32 + t * A_TERM,
                              fA[wy][d][t][0], fA[wy][d][t][1],
                              fA[wy][d][t][2], fA[wy][d][t][3]);
            }
            #pragma unroll
            for (int px = 0; px < 2; px++) {
                #pragma unroll
                for (int ks = 0; ks < 4; ks++) {
                    int wy = ks >> 1, dxx = px + (ks & 1);
                    const u32* aH = fA[wy][dxx][0];
                    const u32* aL = fA[wy][dxx][1];
                    const u32* bh = fB[py][px][0][ks];
                    const u32* bl = fB[py][px][1][ks];
                    mma16816(acc[py][px][0], aH, bh[0], bh[2]);
                    mma16816(acc[py][px][1], aH, bh[1], bh[3]);
                    mma16816(acc[py][px][0], aL, bh[0], bh[2]);
                    mma16816(acc[py][px][1], aL, bh[1], bh[3]);
                    mma16816(acc[py][px][0], aH, bl[0], bl[2]);
                    mma16816(acc[py][px][1], aH, bl[1], bl[3]);
                }
            }
        }

        // epilogue (warp-private, coalesced float2: px parities -> adjacent cols)
        {
            int q = lane >> 2;
            #pragma unroll
            for (int py = 0; py < 2; py++)
                #pragma unroll
                for (int nh = 0; nh < 2; nh++)
                    #pragma unroll
                    for (int j = 0; j < 4; j++) {
                        int p  = (j >= 2) ? q + 8 : q;
                        int oc = 2 * (lane & 3) + 8 * nh + (j & 1);
                        float* ptr = outb + (size_t)oc * 1048576
                                   + (size_t)(2 * i + py) * 1024 + 2 * (cw + p);
                        *(float2*)ptr = make_float2(acc[py][0][nh][j], acc[py][1][nh][j]);
                    }
        }

        // advance pipeline (warp-private; no block sync)
        asm volatile("cp.async.wait_group 0;" ::: "memory");   // raw(i+2) arrived
        if (i + 2 <= i0 + 16) convert_warp(smem, wid, lane, i + 2);
        __syncwarp();
        if (i + 3 <= i0 + 16) {
            stage_raw_warp(rwb, xb, cw, i + 3, lane);
            asm volatile("cp.async.commit_group;" ::: "memory");
        }
    }
}

extern "C" void kernel_launch(void* const* d_in, const int* in_sizes, int n_in,
                              void* d_out, int out_size)
{
    const float* x    = (const float*)d_in[0];
    const float* w    = (const float*)d_in[1];
    const float* bias = (const float*)d_in[2];
    float* out        = (float*)d_out;

    cudaFuncSetAttribute(upconv_hmma2,
                         cudaFuncAttributeMaxDynamicSharedMemorySize, SMEM_TOTAL);

    build_B_kernel<<<16, 256>>>(w);
    upconv_hmma2<<<dim3(4, 32, 8), 256, SMEM_TOTAL>>>(x, bias, out);
}